// round 10
// baseline (speedup 1.0000x reference)
#include <cuda_runtime.h>

#define T_SEQ 8192
#define C_DIM 64
#define B_SZ 2
#define L_CH 64
#define NCH (T_SEQ / L_CH)       /* 128 chunks per batch */
#define NCHT (B_SZ * NCH)        /* 256 chunks total     */
#define SP 68                    /* padded smem row stride (floats); 272B rows, 16B-aligned */
#define TPB 256
#define GAMMA_D 0.96875
#define TILE_F (C_DIM * SP)      /* 4352 floats per padded 64x64 tile */

typedef unsigned long long ull;

/* ---- packed f32x2 helpers (exact RN, bit-identical to scalar FFMA) ------------ */
__device__ __forceinline__ ull bc2(float x) {
    ull r; asm("mov.b64 %0, {%1, %1};" : "=l"(r) : "f"(x)); return r;
}
__device__ __forceinline__ void fma2(ull& a, ull b, ull c) {
    asm("fma.rn.f32x2 %0, %1, %2, %0;" : "+l"(a) : "l"(b), "l"(c));
}
__device__ __forceinline__ float2 up2(ull v) {
    float2 r; asm("mov.b64 {%0, %1}, %2;" : "=f"(r.x), "=f"(r.y) : "l"(v)); return r;
}

/* scratch: M = Wq*Wk^T; per-chunk Y=X*M, G=X^T*Gamma*X, scanned G, masked P^T */
__device__ float g_M [4096];
__device__ float g_Y [NCHT * 4096];
__device__ float g_G [NCHT * 4096];
__device__ float g_Gs[NCHT * 4096];
__device__ float g_Pt[NCHT * 4096];

/* ---- Kernel M: M[c][d] = sum_o WQ[c][o] * WK[d][o]  (4 blocks x 16 rows) ------ */
__global__ __launch_bounds__(TPB) void kM(const float* __restrict__ WQ,
                                          const float* __restrict__ WK) {
    __shared__ float sWkT[64 * SP];   /* WK^T: [o][d] */
    __shared__ float sWq [16 * SP];   /* 16 rows of WQ */
    const int tid = threadIdx.x, blk = blockIdx.x;

    for (int e = tid; e < 1024; e += TPB) {
        int r = e >> 4, c4 = (e & 15) << 2;
        float4 w = *(const float4*)(WK + r * 64 + c4);
        sWkT[(c4+0)*SP + r] = w.x; sWkT[(c4+1)*SP + r] = w.y;
        sWkT[(c4+2)*SP + r] = w.z; sWkT[(c4+3)*SP + r] = w.w;
    }
    {
        int r = tid >> 4, c4 = (tid & 15) << 2;
        *(float4*)(sWq + r * SP + c4) = *(const float4*)(WQ + (blk * 16 + r) * 64 + c4);
    }
    __syncthreads();

    const int ty = tid >> 4, tx = tid & 15;
    float a0 = 0.f, a1 = 0.f, a2 = 0.f, a3 = 0.f;
    #pragma unroll 4
    for (int o = 0; o < 64; ++o) {
        float q = sWq[ty * SP + o];
        float4 w = *(const float4*)(sWkT + o * SP + (tx << 2));
        a0 += q * w.x; a1 += q * w.y; a2 += q * w.z; a3 += q * w.w;
    }
    *(float4*)(g_M + (blk * 16 + ty) * 64 + (tx << 2)) = make_float4(a0, a1, a2, a3);
}

/* ---- Kernel A: Y = X*M ; G = X^T*Gamma*X ; P^T = ((Y*X^T) o D)^T --------------- */
__global__ __launch_bounds__(TPB, 4) void kA(const float* __restrict__ Xin) {
    extern __shared__ float sm[];
    float* sX  = sm;                 /* X row-major                    */
    float* sXt = sm + 1 * TILE_F;    /* X^T                            */
    float* sM  = sm + 2 * TILE_F;    /* M; later reused as Y           */
    float* sgp = sm + 3 * TILE_F;    /* gamma powers 0..64             */

    const int tid = threadIdx.x;
    const int blk = blockIdx.x;
    const int b = blk >> 7, ci = blk & 127;
    const float* Xg = Xin + (size_t)(b * T_SEQ + ci * L_CH) * C_DIM;

    for (int e = tid; e < 1024; e += TPB) {
        int r = e >> 4, c4 = (e & 15) << 2;
        float4 xv = *(const float4*)(Xg + r * 64 + c4);
        *(float4*)(sX + r * SP + c4) = xv;
        sXt[(c4+0)*SP + r] = xv.x; sXt[(c4+1)*SP + r] = xv.y;
        sXt[(c4+2)*SP + r] = xv.z; sXt[(c4+3)*SP + r] = xv.w;
        *(float4*)(sM + r * SP + c4) = *(const float4*)(g_M + r * 64 + c4);
    }
    if (tid == 0) {
        double g = 1.0;
        for (int n = 0; n <= 64; ++n) { sgp[n] = (float)g; g *= GAMMA_D; }
    }
    __syncthreads();

    const int ty = tid >> 4, tx = tid & 15;
    const int r0 = ty << 2, c0 = tx << 2;

    /* loop 1: Y[i][d] = sum_c X[i][c] M[c][d] */
    ull y01[4], y23[4];
    #pragma unroll
    for (int m = 0; m < 4; ++m) { y01[m] = 0ull; y23[m] = 0ull; }
    #pragma unroll 4
    for (int t = 0; t < 64; ++t) {
        ull xb[4];
        #pragma unroll
        for (int m = 0; m < 4; ++m) xb[m] = bc2(sX[(r0 + m) * SP + t]);
        ulonglong2 mr = *(const ulonglong2*)(sM + t * SP + c0);
        #pragma unroll
        for (int m = 0; m < 4; ++m) { fma2(y01[m], xb[m], mr.x); fma2(y23[m], xb[m], mr.y); }
    }
    __syncthreads();                 /* everyone done reading sM */

    float* sY = sM;
    {
        float* Yg = g_Y + blk * 4096;
        #pragma unroll
        for (int m = 0; m < 4; ++m) {
            float2 a = up2(y01[m]), bb = up2(y23[m]);
            float4 v = make_float4(a.x, a.y, bb.x, bb.y);
            *(float4*)(sY + (r0+m)*SP + c0) = v;
            *(float4*)(Yg + (r0+m)*64 + c0) = v;
        }
    }
    __syncthreads();                 /* sY visible to all */

    /* loop 2: G[p][q] = sum_t gamma^(63-t) X[t][p] X[t][q] */
    {
        ull a01[4], a23[4];
        #pragma unroll
        for (int m = 0; m < 4; ++m) { a01[m] = 0ull; a23[m] = 0ull; }
        #pragma unroll 4
        for (int t = 0; t < 64; ++t) {
            float w = sgp[63 - t];
            float4 xp = *(const float4*)(sX + t * SP + r0);   /* X[t][r0..r0+3] */
            ull gb0 = bc2(w * xp.x), gb1 = bc2(w * xp.y);
            ull gb2 = bc2(w * xp.z), gb3 = bc2(w * xp.w);
            ulonglong2 xq = *(const ulonglong2*)(sX + t * SP + c0);
            fma2(a01[0], gb0, xq.x); fma2(a23[0], gb0, xq.y);
            fma2(a01[1], gb1, xq.x); fma2(a23[1], gb1, xq.y);
            fma2(a01[2], gb2, xq.x); fma2(a23[2], gb2, xq.y);
            fma2(a01[3], gb3, xq.x); fma2(a23[3], gb3, xq.y);
        }
        float* Gg = g_G + blk * 4096;
        #pragma unroll
        for (int m = 0; m < 4; ++m) {
            float2 a = up2(a01[m]), bb = up2(a23[m]);
            *(float4*)(Gg + (r0+m)*64 + c0) = make_float4(a.x, a.y, bb.x, bb.y);
        }
    }

    /* loop 3: P[i][j] = sum_d Y[i][d] Xt[d][j], masked; spill P^T */
    {
        ull p01[4], p23[4];
        #pragma unroll
        for (int m = 0; m < 4; ++m) { p01[m] = 0ull; p23[m] = 0ull; }
        #pragma unroll 4
        for (int t = 0; t < 64; ++t) {
            ull yb[4];
            #pragma unroll
            for (int m = 0; m < 4; ++m) yb[m] = bc2(sY[(r0 + m) * SP + t]);
            ulonglong2 xt = *(const ulonglong2*)(sXt + t * SP + c0);
            #pragma unroll
            for (int m = 0; m < 4; ++m) { fma2(p01[m], yb[m], xt.x); fma2(p23[m], yb[m], xt.y); }
        }
        float p[16];
        #pragma unroll
        for (int m = 0; m < 4; ++m) {
            float2 a = up2(p01[m]), bb = up2(p23[m]);
            p[m*4+0]=a.x; p[m*4+1]=a.y; p[m*4+2]=bb.x; p[m*4+3]=bb.y;
        }
        #pragma unroll
        for (int m = 0; m < 4; ++m)
            #pragma unroll
            for (int n = 0; n < 4; ++n) {
                int i = r0 + m, j = c0 + n;
                p[m*4+n] = (i >= j) ? p[m*4+n] * sgp[i - j] : 0.f;
            }
        float* Pg = g_Pt + blk * 4096;
        #pragma unroll
        for (int n = 0; n < 4; ++n)
            *(float4*)(Pg + (c0+n)*64 + r0) = make_float4(p[n], p[4+n], p[8+n], p[12+n]);
    }
}

/* ---------------- Kernel B: scan of G over chunks (per element) ---------------- */
__global__ __launch_bounds__(TPB) void kscan() {
    const int e = blockIdx.x * TPB + threadIdx.x;   /* 0..8191 */
    const int b = e >> 12, idx = e & 4095;
    double gd = 1.0;
    #pragma unroll
    for (int n = 0; n < 64; ++n) gd *= GAMMA_D;
    const float d64 = (float)gd;

    const float* Ab = g_G  + (size_t)b * NCH * 4096 + idx;
    float*       Sb = g_Gs + (size_t)b * NCH * 4096 + idx;
    float s = 0.f;
    for (int c = 0; c < NCH; c += 8) {
        float a[8];
        #pragma unroll
        for (int j = 0; j < 8; ++j) a[j] = Ab[(size_t)(c + j) * 4096];
        #pragma unroll
        for (int j = 0; j < 8; ++j) {
            Sb[(size_t)(c + j) * 4096] = s;     /* state at chunk start */
            s = s * d64 + a[j];
        }
    }
}

/* ---- Kernel C: Z = P*X + Gamma'*Y*Gs ; out = GN(Z*Wv); permuted store --------- */
__global__ __launch_bounds__(TPB, 3) void kC(const float* __restrict__ Xin,
                                             const float* __restrict__ WV,
                                             const float* __restrict__ gnw,
                                             const float* __restrict__ gnb,
                                             float* __restrict__ Out) {
    extern __shared__ float sm[];
    float* sPt = sm;                 /* P^T; later Z                    */
    float* sX  = sm + 1 * TILE_F;
    float* sY  = sm + 2 * TILE_F;
    float* sG  = sm + 3 * TILE_F;    /* G-scanned; later Wv             */
    float* sgp = sm + 4 * TILE_F;

    const int tid = threadIdx.x;
    const int blk = blockIdx.x;
    const int b = blk >> 7, t0 = (blk & 127) << 6;
    const float* Xg = Xin + (size_t)(b * T_SEQ + t0) * C_DIM;

    for (int e = tid; e < 1024; e += TPB) {
        int r = e >> 4, c4 = (e & 15) << 2;
        *(float4*)(sPt + r * SP + c4) = *(const float4*)(g_Pt + blk * 4096 + r * 64 + c4);
        *(float4*)(sX  + r * SP + c4) = *(const float4*)(Xg + r * 64 + c4);
        *(float4*)(sY  + r * SP + c4) = *(const float4*)(g_Y  + blk * 4096 + r * 64 + c4);
        *(float4*)(sG  + r * SP + c4) = *(const float4*)(g_Gs + blk * 4096 + r * 64 + c4);
    }
    if (tid == 0) {
        double g = 1.0;
        for (int n = 0; n <= 64; ++n) { sgp[n] = (float)g; g *= GAMMA_D; }
    }
    __syncthreads();

    const int ty = tid >> 4, tx = tid & 15;
    const int r0 = ty << 2, c0 = tx << 2;

    const float4 gw4 = *(const float4*)(gnw + c0);
    const float4 gb4 = *(const float4*)(gnb + c0);

    /* fused: Z1[i][c] = sum_j Pt[j][i] X[j][c] ; Z2[i][c] = sum_k Y[i][k] G[k][c] */
    ull z1a[4], z1b[4], z2a[4], z2b[4];
    #pragma unroll
    for (int m = 0; m < 4; ++m) { z1a[m]=0ull; z1b[m]=0ull; z2a[m]=0ull; z2b[m]=0ull; }
    #pragma unroll 2
    for (int t = 0; t < 64; ++t) {
        float4 pt4 = *(const float4*)(sPt + t * SP + r0);   /* P^T[t][r0..r0+3] */
        ull pb0 = bc2(pt4.x), pb1 = bc2(pt4.y), pb2 = bc2(pt4.z), pb3 = bc2(pt4.w);
        ulonglong2 xv = *(const ulonglong2*)(sX + t * SP + c0);
        fma2(z1a[0], pb0, xv.x); fma2(z1b[0], pb0, xv.y);
        fma2(z1a[1], pb1, xv.x); fma2(z1b[1], pb1, xv.y);
        fma2(z1a[2], pb2, xv.x); fma2(z1b[2], pb2, xv.y);
        fma2(z1a[3], pb3, xv.x); fma2(z1b[3], pb3, xv.y);
        ull yb[4];
        #pragma unroll
        for (int m = 0; m < 4; ++m) yb[m] = bc2(sY[(r0 + m) * SP + t]);
        ulonglong2 gv = *(const ulonglong2*)(sG + t * SP + c0);
        #pragma unroll
        for (int m = 0; m < 4; ++m) { fma2(z2a[m], yb[m], gv.x); fma2(z2b[m], yb[m], gv.y); }
    }

    float z[16];
    #pragma unroll
    for (int m = 0; m < 4; ++m) {
        float ge = sgp[r0 + m + 1];
        float2 a1 = up2(z1a[m]), b1 = up2(z1b[m]);
        float2 a2 = up2(z2a[m]), b2 = up2(z2b[m]);
        z[m*4+0] = a1.x + ge * a2.x;
        z[m*4+1] = a1.y + ge * a2.y;
        z[m*4+2] = b1.x + ge * b2.x;
        z[m*4+3] = b1.y + ge * b2.y;
    }
    __syncthreads();                 /* sPt/sG reads done */

    float* sZ  = sPt;
    float* sWv = sG;
    #pragma unroll
    for (int m = 0; m < 4; ++m)
        *(float4*)(sZ + (r0+m)*SP + c0) = make_float4(z[m*4], z[m*4+1], z[m*4+2], z[m*4+3]);
    for (int e = tid; e < 1024; e += TPB) {
        int r = e >> 4, c4 = (e & 15) << 2;
        *(float4*)(sWv + r * SP + c4) = *(const float4*)(WV + r * 64 + c4);
    }
    __syncthreads();

    /* out[i][c] = sum_k Z[i][k] Wv[k][c] */
    ull o01[4], o23[4];
    #pragma unroll
    for (int m = 0; m < 4; ++m) { o01[m] = 0ull; o23[m] = 0ull; }
    #pragma unroll 4
    for (int k = 0; k < 64; ++k) {
        ull zb[4];
        #pragma unroll
        for (int m = 0; m < 4; ++m) zb[m] = bc2(sZ[(r0 + m) * SP + k]);
        ulonglong2 wv = *(const ulonglong2*)(sWv + k * SP + c0);
        #pragma unroll
        for (int m = 0; m < 4; ++m) { fma2(o01[m], zb[m], wv.x); fma2(o23[m], zb[m], wv.y); }
    }
    float o[16];
    #pragma unroll
    for (int m = 0; m < 4; ++m) {
        float2 a = up2(o01[m]), bb = up2(o23[m]);
        o[m*4+0]=a.x; o[m*4+1]=a.y; o[m*4+2]=bb.x; o[m*4+3]=bb.y;
    }

    /* GroupNorm: thread's 4 channels + lane-partner's 4 = one 8-channel group */
    const float gwv[4] = { gw4.x, gw4.y, gw4.z, gw4.w };
    const float gbv[4] = { gb4.x, gb4.y, gb4.z, gb4.w };
    #pragma unroll
    for (int m = 0; m < 4; ++m) {
        float s_ = o[m*4] + o[m*4+1] + o[m*4+2] + o[m*4+3];
        float q_ = o[m*4]*o[m*4] + o[m*4+1]*o[m*4+1] + o[m*4+2]*o[m*4+2] + o[m*4+3]*o[m*4+3];
        s_ += __shfl_xor_sync(0xffffffffu, s_, 1);
        q_ += __shfl_xor_sync(0xffffffffu, q_, 1);
        float mu  = s_ * 0.125f;
        float var = q_ * 0.125f - mu * mu;      /* biased, matches GroupNorm */
        float inv = rsqrtf(var + 1e-6f);
        #pragma unroll
        for (int n = 0; n < 4; ++n)
            o[m*4+n] = (o[m*4+n] - mu) * inv * gwv[n] + gbv[n];
    }

    /* permuted store Out[b][c][t]: per channel, 4 consecutive t as STG.128 */
    float* Ob = Out + (size_t)b * C_DIM * T_SEQ + t0 + r0;
    #pragma unroll
    for (int n = 0; n < 4; ++n)
        *(float4*)(Ob + (size_t)(c0 + n) * T_SEQ) = make_float4(o[n], o[4+n], o[8+n], o[12+n]);
}

extern "C" void kernel_launch(void* const* d_in, const int* in_sizes, int n_in,
                              void* d_out, int out_size) {
    const float* Q_in = (const float*)d_in[0];
    const float* W_Q  = (const float*)d_in[1];
    const float* W_K  = (const float*)d_in[2];
    const float* W_V  = (const float*)d_in[3];
    const float* gnw  = (const float*)d_in[4];
    const float* gnb  = (const float*)d_in[5];
    float* out = (float*)d_out;

    const int smemA = (3 * TILE_F + 72) * (int)sizeof(float);   /* 52512 B */
    const int smemC = (4 * TILE_F + 72) * (int)sizeof(float);   /* 69920 B */
    cudaFuncSetAttribute(kA, cudaFuncAttributeMaxDynamicSharedMemorySize, smemA);
    cudaFuncSetAttribute(kC, cudaFuncAttributeMaxDynamicSharedMemorySize, smemC);

    kM<<<4, TPB>>>(W_Q, W_K);
    kA<<<NCHT, TPB, smemA>>>(Q_in);
    kscan<<<32, TPB>>>();
    kC<<<NCHT, TPB, smemC>>>(Q_in, W_V, gnw, gnb, out);
}

// round 17
// speedup vs baseline: 1.3454x; 1.3454x over previous
#include <cuda_runtime.h>

#define T_SEQ 8192
#define C_DIM 64
#define B_SZ 2
#define L_CH 64
#define NCH (T_SEQ / L_CH)       /* 128 chunks per batch */
#define NCHT (B_SZ * NCH)        /* 256 chunks total = grid size */
#define SP 68                    /* padded smem row stride (floats); 272B rows */
#define TPB 256
#define GAMMA_D 0.96875
#define TILE_F (C_DIM * SP)      /* 4352 floats per padded 64x64 tile */
#define WIN 10                   /* truncation: d64^10 ~ 1.5e-9 relative */

typedef unsigned long long ull;

/* ---- packed f32x2 helpers (exact RN, bit-identical to scalar FFMA) ------------ */
__device__ __forceinline__ ull bc2(float x) {
    ull r; asm("mov.b64 %0, {%1, %1};" : "=l"(r) : "f"(x)); return r;
}
__device__ __forceinline__ void fma2(ull& a, ull b, ull c) {
    asm("fma.rn.f32x2 %0, %1, %2, %0;" : "+l"(a) : "l"(b), "l"(c));
}
__device__ __forceinline__ float2 up2(ull v) {
    float2 r; asm("mov.b64 {%0, %1}, %2;" : "=f"(r.x), "=f"(r.y) : "l"(v)); return r;
}

/* per-chunk decayed KV sums + producer flags (monotone, replay-safe epochs) */
__device__ float    g_A[NCHT * 4096];
__device__ unsigned g_flag[NCHT];    /* incremented once per execution after A write */
__device__ unsigned g_exec[NCHT];    /* per-CTA execution counter (epoch source)    */

__global__ __launch_bounds__(TPB, 2) void retnet_win(
        const float* __restrict__ Xin,
        const float* __restrict__ WQ,
        const float* __restrict__ WK,
        const float* __restrict__ WV,
        const float* __restrict__ gnw,
        const float* __restrict__ gnb,
        float* __restrict__ Out) {
    extern __shared__ float sm[];
    float* T0  = sm;                 /* X -> K^T -> S                    */
    float* T1  = sm + 1 * TILE_F;    /* WQ -> Q                          */
    float* T2  = sm + 2 * TILE_F;    /* WK -> Kd -> P                    */
    float* T3  = sm + 3 * TILE_F;    /* WV -> V                          */
    float* sgp = sm + 4 * TILE_F;    /* gamma powers 0..64               */
    __shared__ unsigned sh_epoch;

    const int tid = threadIdx.x;
    const int blk = blockIdx.x;            /* 0..255 */
    const int b = blk >> 7, ci = blk & 127;
    const int t0g = ci * L_CH;
    const float* Xg = Xin + (size_t)(b * T_SEQ + t0g) * C_DIM;

    /* ---------------- load X + weights ---------------- */
    for (int e = tid; e < 1024; e += TPB) {
        int r = e >> 4, c4 = (e & 15) << 2;
        *(float4*)(T0 + r * SP + c4) = *(const float4*)(Xg + r * 64 + c4);
        *(float4*)(T1 + r * SP + c4) = *(const float4*)(WQ + r * 64 + c4);
        *(float4*)(T2 + r * SP + c4) = *(const float4*)(WK + r * 64 + c4);
        *(float4*)(T3 + r * SP + c4) = *(const float4*)(WV + r * 64 + c4);
    }
    if (tid == 0) {
        double g = 1.0;
        for (int n = 0; n <= 64; ++n) { sgp[n] = (float)g; g *= GAMMA_D; }
        sh_epoch = atomicAdd(&g_exec[blk], 1u) + 1u;   /* this execution's epoch */
    }
    __syncthreads();
    const unsigned epoch = sh_epoch;

    const int ty = tid >> 4, tx = tid & 15;
    const int r0 = ty << 2, c0 = tx << 2;

    /* fused Q,K,V projections: thread = rows r0..r0+3 x cols c0..c0+3 */
    ull q01[4], q23[4], k01[4], k23[4], v01[4], v23[4];
    #pragma unroll
    for (int m = 0; m < 4; ++m) {
        q01[m]=0ull; q23[m]=0ull; k01[m]=0ull; k23[m]=0ull; v01[m]=0ull; v23[m]=0ull;
    }
    #pragma unroll 4
    for (int k = 0; k < 64; ++k) {
        ull xb[4];
        #pragma unroll
        for (int m = 0; m < 4; ++m) xb[m] = bc2(T0[(r0 + m) * SP + k]);
        ulonglong2 wq = *(const ulonglong2*)(T1 + k * SP + c0);
        ulonglong2 wk = *(const ulonglong2*)(T2 + k * SP + c0);
        ulonglong2 wv = *(const ulonglong2*)(T3 + k * SP + c0);
        #pragma unroll
        for (int m = 0; m < 4; ++m) {
            fma2(q01[m], xb[m], wq.x); fma2(q23[m], xb[m], wq.y);
            fma2(k01[m], xb[m], wk.x); fma2(k23[m], xb[m], wk.y);
            fma2(v01[m], xb[m], wv.x); fma2(v23[m], xb[m], wv.y);
        }
    }
    __syncthreads();                 /* X + W tiles dead */

    /* unpack; stage Q, Kd (decayed), V, K^T into smem */
    float qf[16], kf[16], vf[16];
    #pragma unroll
    for (int m = 0; m < 4; ++m) {
        float2 a = up2(q01[m]), bb = up2(q23[m]);
        qf[m*4+0]=a.x; qf[m*4+1]=a.y; qf[m*4+2]=bb.x; qf[m*4+3]=bb.y;
        float2 c = up2(k01[m]), d = up2(k23[m]);
        kf[m*4+0]=c.x; kf[m*4+1]=c.y; kf[m*4+2]=d.x; kf[m*4+3]=d.y;
        float2 e = up2(v01[m]), f = up2(v23[m]);
        vf[m*4+0]=e.x; vf[m*4+1]=e.y; vf[m*4+2]=f.x; vf[m*4+3]=f.y;
    }
    float* sQ  = T1;
    float* sKd = T2;
    float* sV  = T3;
    float* sKt = T0;
    #pragma unroll
    for (int m = 0; m < 4; ++m) {
        float w = sgp[63 - (r0 + m)];
        *(float4*)(sQ  + (r0+m)*SP + c0) = make_float4(qf[m*4], qf[m*4+1], qf[m*4+2], qf[m*4+3]);
        *(float4*)(sKd + (r0+m)*SP + c0) = make_float4(kf[m*4]*w, kf[m*4+1]*w, kf[m*4+2]*w, kf[m*4+3]*w);
        *(float4*)(sV  + (r0+m)*SP + c0) = make_float4(vf[m*4], vf[m*4+1], vf[m*4+2], vf[m*4+3]);
    }
    #pragma unroll
    for (int n = 0; n < 4; ++n)        /* K^T[d][i] */
        *(float4*)(sKt + (c0+n)*SP + r0) = make_float4(kf[n], kf[4+n], kf[8+n], kf[12+n]);
    __syncthreads();

    /* A[p][c] = sum_i Kd[i][p] V[i][c]  -> g_A  (producers never wait on anyone) */
    {
        ull a01[4], a23[4];
        #pragma unroll
        for (int m = 0; m < 4; ++m) { a01[m] = 0ull; a23[m] = 0ull; }
        #pragma unroll 4
        for (int i = 0; i < 64; ++i) {
            ull kd[4];
            #pragma unroll
            for (int m = 0; m < 4; ++m) kd[m] = bc2(sKd[i * SP + r0 + m]);
            ulonglong2 vv = *(const ulonglong2*)(sV + i * SP + c0);
            #pragma unroll
            for (int m = 0; m < 4; ++m) { fma2(a01[m], kd[m], vv.x); fma2(a23[m], kd[m], vv.y); }
        }
        float* Ag = g_A + blk * 4096;
        #pragma unroll
        for (int m = 0; m < 4; ++m) {
            float2 a = up2(a01[m]), bb = up2(a23[m]);
            *(float4*)(Ag + (r0+m)*64 + c0) = make_float4(a.x, a.y, bb.x, bb.y);
        }
    }
    /* release: every thread fences its A stores, then one thread bumps the flag */
    __threadfence();
    __syncthreads();
    if (tid == 0) atomicAdd(&g_flag[blk], 1u);

    /* P[i][j] = (sum_d Q[i][d] Kt[d][j]) o D  (overlaps neighbors' A production) */
    float p[16];
    {
        ull p01[4], p23[4];
        #pragma unroll
        for (int m = 0; m < 4; ++m) { p01[m] = 0ull; p23[m] = 0ull; }
        #pragma unroll 4
        for (int d = 0; d < 64; ++d) {
            ull qb[4];
            #pragma unroll
            for (int m = 0; m < 4; ++m) qb[m] = bc2(sQ[(r0 + m) * SP + d]);
            ulonglong2 kt = *(const ulonglong2*)(sKt + d * SP + c0);
            #pragma unroll
            for (int m = 0; m < 4; ++m) { fma2(p01[m], qb[m], kt.x); fma2(p23[m], qb[m], kt.y); }
        }
        #pragma unroll
        for (int m = 0; m < 4; ++m) {
            float2 a = up2(p01[m]), bb = up2(p23[m]);
            p[m*4+0]=a.x; p[m*4+1]=a.y; p[m*4+2]=bb.x; p[m*4+3]=bb.y;
        }
        #pragma unroll
        for (int m = 0; m < 4; ++m)
            #pragma unroll
            for (int n = 0; n < 4; ++n) {
                int i = r0 + m, j = c0 + n;
                p[m*4+n] = (i >= j) ? p[m*4+n] * sgp[i - j] : 0.f;
            }
    }
    float* sP = sKd;                 /* T2's last reader (A GEMM) finished pre-flag-sync */
    #pragma unroll
    for (int m = 0; m < 4; ++m)
        *(float4*)(sP + (r0+m)*SP + c0) = make_float4(p[m*4], p[m*4+1], p[m*4+2], p[m*4+3]);

    /* consumer wait: only lower-bid neighbors; bounded spin (hang -> visible fail) */
    const int wmax = (ci < WIN) ? ci : WIN;
    if (tid == 0) {
        for (int w = 1; w <= wmax; ++w) {
            volatile unsigned* f = (volatile unsigned*)&g_flag[blk - w];
            int guard = 0;
            while (*f < epoch && guard < 20000000) { __nanosleep(64); ++guard; }
        }
    }
    __syncthreads();                 /* also: all P-GEMM reads of sKt (T0) done */
    __threadfence();                 /* acquire side */

    /* window state at chunk start:
       S = sum_{w=1..wmax} d64^(w-1) * A_{ci-w}   (w=1 coefficient is 1 —
       neighbor-internal decay gamma^{63-j} and our gamma^{i+1} already span
       the full token distance; exact match to the scan recurrence)        */
    float* sS = T0;
    {
        double gd = 1.0;
        #pragma unroll
        for (int n = 0; n < 64; ++n) gd *= GAMMA_D;
        const float d64 = (float)gd;
        float S16[16];
        #pragma unroll
        for (int u = 0; u < 16; ++u) S16[u] = 0.f;
        float pw = 1.0f;                       /* d64^(w-1), starts at 1 */
        for (int w = 1; w <= wmax; ++w) {
            const float* Aw = g_A + (size_t)(blk - w) * 4096;
            #pragma unroll
            for (int m = 0; m < 4; ++m) {
                float4 av = __ldcg((const float4*)(Aw + (r0 + m) * 64 + c0));
                S16[m*4+0] += pw * av.x; S16[m*4+1] += pw * av.y;
                S16[m*4+2] += pw * av.z; S16[m*4+3] += pw * av.w;
            }
            pw *= d64;
        }
        #pragma unroll
        for (int m = 0; m < 4; ++m)
            *(float4*)(sS + (r0+m)*SP + c0) = make_float4(S16[m*4], S16[m*4+1], S16[m*4+2], S16[m*4+3]);
    }
    __syncthreads();

    /* out = P*V + gamma^(i+1) * Q*S */
    ull o1a[4], o1b[4], o2a[4], o2b[4];
    #pragma unroll
    for (int m = 0; m < 4; ++m) { o1a[m]=0ull; o1b[m]=0ull; o2a[m]=0ull; o2b[m]=0ull; }
    #pragma unroll 2
    for (int j = 0; j < 64; ++j) {
        ull pm[4], qm[4];
        #pragma unroll
        for (int m = 0; m < 4; ++m) {
            pm[m] = bc2(sP[(r0 + m) * SP + j]);
            qm[m] = bc2(sQ[(r0 + m) * SP + j]);
        }
        ulonglong2 v = *(const ulonglong2*)(sV + j * SP + c0);
        ulonglong2 s = *(const ulonglong2*)(sS + j * SP + c0);
        #pragma unroll
        for (int m = 0; m < 4; ++m) {
            fma2(o1a[m], pm[m], v.x); fma2(o1b[m], pm[m], v.y);
            fma2(o2a[m], qm[m], s.x); fma2(o2b[m], qm[m], s.y);
        }
    }

    float o[16];
    #pragma unroll
    for (int m = 0; m < 4; ++m) {
        float ge = sgp[r0 + m + 1];
        float2 a1 = up2(o1a[m]), b1 = up2(o1b[m]);
        float2 a2 = up2(o2a[m]), b2 = up2(o2b[m]);
        o[m*4+0] = a1.x + ge * a2.x;
        o[m*4+1] = a1.y + ge * a2.y;
        o[m*4+2] = b1.x + ge * b2.x;
        o[m*4+3] = b1.y + ge * b2.y;
    }

    /* GroupNorm: thread's 4 channels + lane-partner's 4 = one 8-channel group */
    const float4 gw4 = *(const float4*)(gnw + c0);
    const float4 gb4 = *(const float4*)(gnb + c0);
    const float gwv[4] = { gw4.x, gw4.y, gw4.z, gw4.w };
    const float gbv[4] = { gb4.x, gb4.y, gb4.z, gb4.w };
    #pragma unroll
    for (int m = 0; m < 4; ++m) {
        float s_ = o[m*4] + o[m*4+1] + o[m*4+2] + o[m*4+3];
        float q_ = o[m*4]*o[m*4] + o[m*4+1]*o[m*4+1] + o[m*4+2]*o[m*4+2] + o[m*4+3]*o[m*4+3];
        s_ += __shfl_xor_sync(0xffffffffu, s_, 1);
        q_ += __shfl_xor_sync(0xffffffffu, q_, 1);
        float mu  = s_ * 0.125f;
        float var = q_ * 0.125f - mu * mu;      /* biased, matches GroupNorm */
        float inv = rsqrtf(var + 1e-6f);
        #pragma unroll
        for (int n = 0; n < 4; ++n)
            o[m*4+n] = (o[m*4+n] - mu) * inv * gwv[n] + gbv[n];
    }

    /* permuted store Out[b][c][t]: per channel, 4 consecutive t as STG.128 */
    float* Ob = Out + (size_t)b * C_DIM * T_SEQ + t0g + r0;
    #pragma unroll
    for (int n = 0; n < 4; ++n)
        *(float4*)(Ob + (size_t)(c0 + n) * T_SEQ) = make_float4(o[n], o[4+n], o[8+n], o[12+n]);
}

extern "C" void kernel_launch(void* const* d_in, const int* in_sizes, int n_in,
                              void* d_out, int out_size) {
    const float* Q_in = (const float*)d_in[0];
    const float* W_Q  = (const float*)d_in[1];
    const float* W_K  = (const float*)d_in[2];
    const float* W_V  = (const float*)d_in[3];
    const float* gnw  = (const float*)d_in[4];
    const float* gnb  = (const float*)d_in[5];
    float* out = (float*)d_out;

    const int smemF = (4 * TILE_F + 72) * (int)sizeof(float);   /* 69920 B */
    cudaFuncSetAttribute(retnet_win, cudaFuncAttributeMaxDynamicSharedMemorySize, smemF);

    retnet_win<<<NCHT, TPB, smemF>>>(Q_in, W_Q, W_K, W_V, gnw, gnb, out);
}